// round 3
// baseline (speedup 1.0000x reference)
#include <cuda_runtime.h>
#include <math.h>

#define U 8388608UL
__device__ __align__(256) float g_pool[11*U + 131072];

// ---------------- DWT: x (16,128,128,128) -> token-major yL,yHH, hllh(256ch) ----------------
__global__ void dwt_kernel(const float* __restrict__ x, float* __restrict__ hllh,
                           float* __restrict__ yL, float* __restrict__ yHH)
{
    int i  = blockIdx.x;      // out row 0..63
    int cb = blockIdx.y;      // channel block (16 ch)
    int b  = blockIdx.z;
    __shared__ float s[16][2][129];
    int tid = threadIdx.x;
    #pragma unroll
    for (int k = 0; k < 16; k++) {
        int e = tid + k*256;
        int cc = e >> 8, r = (e >> 7) & 1, col = e & 127;
        s[cc][r][col] = x[(((size_t)(b*128 + cb*16 + cc))*128 + 2*i + r)*128 + col];
    }
    __syncthreads();
    #pragma unroll
    for (int k = 0; k < 4; k++) {
        int e = tid + k*256;
        int cc = e & 15, j = e >> 4;
        float a  = s[cc][0][2*j], bb = s[cc][0][2*j+1];
        float c_ = s[cc][1][2*j], d  = s[cc][1][2*j+1];
        size_t token = (size_t)b*4096 + (size_t)i*64 + j;
        int c = cb*16 + cc;
        yL [token*128 + c]        = (a+bb+c_+d)*0.5f;
        yHH[token*128 + c]        = (a-bb-c_+d)*0.5f;
        hllh[token*256 + c]       = (a-bb+c_-d)*0.5f;   // HL
        hllh[token*256 + 128 + c] = (a+bb-c_-d)*0.5f;   // LH
    }
}

// ---------------- generic NT GEMM, BM=BN=128, BK=16, 8x8/thread ----------------
// C = epi(scale*A.B^T + bias) - aux ; epi: 0 none, 1 gelu(exact), 2 sigmoid
__global__ __launch_bounds__(256) void gemm_nt(
    const float* __restrict__ A, size_t sAz, int lda,
    const float* __restrict__ B, size_t sBz, int ldb,
    float* __restrict__ C, size_t sCz, int ldc,
    int K, float scale, const float* __restrict__ bias,
    int epi, const float* __restrict__ aux)
{
    const float* Ab = A + (size_t)blockIdx.z * sAz;
    const float* Bb = B + (size_t)blockIdx.z * sBz;
    float* Cb = C + (size_t)blockIdx.z * sCz;
    int m0 = blockIdx.x * 128, n0 = blockIdx.y * 128;
    __shared__ float As[16][132], Bs[16][132];
    int tid = threadIdx.x, tx = tid & 15, ty = tid >> 4;
    float acc[8][8];
    #pragma unroll
    for (int i = 0; i < 8; i++)
        #pragma unroll
        for (int j = 0; j < 8; j++) acc[i][j] = 0.f;

    int rowA = tid >> 2, kq = (tid & 3) * 4;
    for (int k0 = 0; k0 < K; k0 += 16) {
        #pragma unroll
        for (int e = 0; e < 2; e++) {
            int r = rowA + e*64;
            float4 va = *(const float4*)&Ab[(size_t)(m0 + r)*lda + k0 + kq];
            As[kq+0][r]=va.x; As[kq+1][r]=va.y; As[kq+2][r]=va.z; As[kq+3][r]=va.w;
            float4 vb = *(const float4*)&Bb[(size_t)(n0 + r)*ldb + k0 + kq];
            Bs[kq+0][r]=vb.x; Bs[kq+1][r]=vb.y; Bs[kq+2][r]=vb.z; Bs[kq+3][r]=vb.w;
        }
        __syncthreads();
        #pragma unroll
        for (int kk = 0; kk < 16; kk++) {
            float a[8], bv[8];
            float4 a0 = *(const float4*)&As[kk][ty*8];
            float4 a1 = *(const float4*)&As[kk][ty*8+4];
            float4 b0 = *(const float4*)&Bs[kk][tx*8];
            float4 b1 = *(const float4*)&Bs[kk][tx*8+4];
            a[0]=a0.x;a[1]=a0.y;a[2]=a0.z;a[3]=a0.w;a[4]=a1.x;a[5]=a1.y;a[6]=a1.z;a[7]=a1.w;
            bv[0]=b0.x;bv[1]=b0.y;bv[2]=b0.z;bv[3]=b0.w;bv[4]=b1.x;bv[5]=b1.y;bv[6]=b1.z;bv[7]=b1.w;
            #pragma unroll
            for (int i = 0; i < 8; i++)
                #pragma unroll
                for (int j = 0; j < 8; j++)
                    acc[i][j] += a[i]*bv[j];
        }
        __syncthreads();
    }
    #pragma unroll
    for (int i = 0; i < 8; i++) {
        int m = m0 + ty*8 + i;
        #pragma unroll
        for (int j = 0; j < 8; j++) {
            int n = n0 + tx*8 + j;
            float v = acc[i][j]*scale;
            if (bias) v += bias[n];
            if (epi == 1) v = v * normcdff(v);
            else if (epi == 2) v = 1.0f/(1.0f + expf(-v));
            if (aux) v -= aux[(size_t)m*ldc + n];
            acc[i][j] = v;
        }
        float* cp = &Cb[(size_t)m*ldc + n0 + tx*8];
        *(float4*)cp     = make_float4(acc[i][0],acc[i][1],acc[i][2],acc[i][3]);
        *(float4*)(cp+4) = make_float4(acc[i][4],acc[i][5],acc[i][6],acc[i][7]);
    }
}

// ---------------- column softmax stats (softmax over q axis) ----------------
__global__ void col_stats(const float* __restrict__ S, float* __restrict__ cmax, float* __restrict__ csum)
{
    int g = blockIdx.x*256 + threadIdx.x;       // 65536 columns
    int z = g >> 9, ki = g & 511;
    const float* col = S + (size_t)z*262144 + ki;
    float m = -1e30f;
    for (int q = 0; q < 512; q++) m = fmaxf(m, col[(size_t)q*512]);
    float s = 0.f;
    for (int q = 0; q < 512; q++) s += expf(col[(size_t)q*512] - m);
    cmax[g] = m; csum[g] = s;
}

// ---------------- PV GEMM: O[q,c] = sum_k exp(S[q,k]-max[k]) * V[k,c]/sum[k] ----------------
__global__ __launch_bounds__(256) void gemm_pv(
    const float* __restrict__ S, const float* __restrict__ V,
    const float* __restrict__ cmax, const float* __restrict__ csum,
    float* __restrict__ O)
{
    int z = blockIdx.z;
    int m0 = blockIdx.x*128;
    const float* Sz = S + (size_t)z*262144;
    const float* Vz = V + (size_t)z*65536;
    const float* cm = cmax + z*512;
    const float* cs = csum + z*512;
    float* Oz = O + (size_t)z*65536;
    __shared__ float As[16][132], Bs[16][132];
    int tid = threadIdx.x, tx = tid & 15, ty = tid >> 4;
    float acc[8][8];
    #pragma unroll
    for (int i = 0; i < 8; i++)
        #pragma unroll
        for (int j = 0; j < 8; j++) acc[i][j] = 0.f;

    int rowA = tid >> 2, kq = (tid & 3) * 4;
    int n4 = (tid & 31) * 4, kkB = tid >> 5;
    for (int k0 = 0; k0 < 512; k0 += 16) {
        #pragma unroll
        for (int e = 0; e < 2; e++) {
            int r = rowA + e*64;
            float4 va = *(const float4*)&Sz[(size_t)(m0+r)*512 + k0 + kq];
            As[kq+0][r] = expf(va.x - cm[k0+kq+0]);
            As[kq+1][r] = expf(va.y - cm[k0+kq+1]);
            As[kq+2][r] = expf(va.z - cm[k0+kq+2]);
            As[kq+3][r] = expf(va.w - cm[k0+kq+3]);
            int kk = kkB + e*8;
            float rs = 1.0f / cs[k0+kk];
            float4 vb = *(const float4*)&Vz[(size_t)(k0+kk)*128 + n4];
            *(float4*)&Bs[kk][n4] = make_float4(vb.x*rs, vb.y*rs, vb.z*rs, vb.w*rs);
        }
        __syncthreads();
        #pragma unroll
        for (int kk = 0; kk < 16; kk++) {
            float a[8], bv[8];
            float4 a0 = *(const float4*)&As[kk][ty*8];
            float4 a1 = *(const float4*)&As[kk][ty*8+4];
            float4 b0 = *(const float4*)&Bs[kk][tx*8];
            float4 b1 = *(const float4*)&Bs[kk][tx*8+4];
            a[0]=a0.x;a[1]=a0.y;a[2]=a0.z;a[3]=a0.w;a[4]=a1.x;a[5]=a1.y;a[6]=a1.z;a[7]=a1.w;
            bv[0]=b0.x;bv[1]=b0.y;bv[2]=b0.z;bv[3]=b0.w;bv[4]=b1.x;bv[5]=b1.y;bv[6]=b1.z;bv[7]=b1.w;
            #pragma unroll
            for (int i = 0; i < 8; i++)
                #pragma unroll
                for (int j = 0; j < 8; j++)
                    acc[i][j] += a[i]*bv[j];
        }
        __syncthreads();
    }
    #pragma unroll
    for (int i = 0; i < 8; i++) {
        int m = m0 + ty*8 + i;
        float* cp = &Oz[(size_t)m*128 + tx*8];
        *(float4*)cp     = make_float4(acc[i][0],acc[i][1],acc[i][2],acc[i][3]);
        *(float4*)(cp+4) = make_float4(acc[i][4],acc[i][5],acc[i][6],acc[i][7]);
    }
}

// ---------------- dual layernorm (ln1, ln3 share stats) ----------------
__global__ void ln_dual(const float* __restrict__ X,
                        const float* __restrict__ g1v, const float* __restrict__ b1v,
                        const float* __restrict__ g3v, const float* __restrict__ b3v,
                        float* __restrict__ t1, float* __restrict__ t3)
{
    int wrp = threadIdx.x >> 5, lane = threadIdx.x & 31;
    size_t token = (size_t)blockIdx.x*8 + wrp;
    const float4 v = *(const float4*)&X[token*128 + lane*4];
    float s  = v.x+v.y+v.z+v.w;
    float ss = v.x*v.x+v.y*v.y+v.z*v.z+v.w*v.w;
    #pragma unroll
    for (int o = 16; o; o >>= 1) {
        s  += __shfl_xor_sync(0xffffffffu, s,  o);
        ss += __shfl_xor_sync(0xffffffffu, ss, o);
    }
    float mean = s * (1.f/128.f);
    float rstd = rsqrtf(ss*(1.f/128.f) - mean*mean + 1e-5f);
    float4 G = *(const float4*)&g1v[lane*4];
    float4 Bv = *(const float4*)&b1v[lane*4];
    float4 o1;
    o1.x = (v.x-mean)*rstd*G.x + Bv.x;
    o1.y = (v.y-mean)*rstd*G.y + Bv.y;
    o1.z = (v.z-mean)*rstd*G.z + Bv.z;
    o1.w = (v.w-mean)*rstd*G.w + Bv.w;
    *(float4*)&t1[token*128 + lane*4] = o1;
    G  = *(const float4*)&g3v[lane*4];
    Bv = *(const float4*)&b3v[lane*4];
    o1.x = (v.x-mean)*rstd*G.x + Bv.x;
    o1.y = (v.y-mean)*rstd*G.y + Bv.y;
    o1.z = (v.z-mean)*rstd*G.z + Bv.z;
    o1.w = (v.w-mean)*rstd*G.w + Bv.w;
    *(float4*)&t3[token*128 + lane*4] = o1;
}

// ---------------- out = gate * ln(x2+x3) ----------------
__global__ void ln_final(const float* __restrict__ X2, const float* __restrict__ X3,
                         const float* __restrict__ G, const float* __restrict__ gv,
                         const float* __restrict__ bv, float* __restrict__ out)
{
    int wrp = threadIdx.x >> 5, lane = threadIdx.x & 31;
    size_t token = (size_t)blockIdx.x*8 + wrp;
    float4 a = *(const float4*)&X2[token*128 + lane*4];
    float4 c = *(const float4*)&X3[token*128 + lane*4];
    float4 v = make_float4(a.x+c.x, a.y+c.y, a.z+c.z, a.w+c.w);
    float s  = v.x+v.y+v.z+v.w;
    float ss = v.x*v.x+v.y*v.y+v.z*v.z+v.w*v.w;
    #pragma unroll
    for (int o = 16; o; o >>= 1) {
        s  += __shfl_xor_sync(0xffffffffu, s,  o);
        ss += __shfl_xor_sync(0xffffffffu, ss, o);
    }
    float mean = s * (1.f/128.f);
    float rstd = rsqrtf(ss*(1.f/128.f) - mean*mean + 1e-5f);
    float4 g = *(const float4*)&gv[lane*4];
    float4 b = *(const float4*)&bv[lane*4];
    float4 gt = *(const float4*)&G[token*128 + lane*4];
    float4 o;
    o.x = gt.x * ((v.x-mean)*rstd*g.x + b.x);
    o.y = gt.y * ((v.y-mean)*rstd*g.y + b.y);
    o.z = gt.z * ((v.z-mean)*rstd*g.z + b.z);
    o.w = gt.w * ((v.w-mean)*rstd*g.w + b.w);
    *(float4*)&out[token*128 + lane*4] = o;
}

// ---------------- l1 conv: 4x4, stride 2, pad 1, relu -> dw token-major ----------------
__global__ __launch_bounds__(256) void conv_l1_kernel(
    const float* __restrict__ x, const float* __restrict__ w,
    const float* __restrict__ bias, float* __restrict__ dw)
{
    int ohp = blockIdx.x;     // 0..31 (pairs of output rows)
    int coh = blockIdx.y;     // 0..1  (64 output channels)
    int b   = blockIdx.z;
    int oh0 = ohp*2;
    int co_base = coh*64;
    __shared__ float patch[4][6][132];
    __shared__ float wts[64][65];
    int tid = threadIdx.x;
    int tco = tid & 15, tpos = tid >> 4;
    int ohl = tpos >> 3, owb = (tpos & 7)*8;
    float acc[4][8];
    #pragma unroll
    for (int i = 0; i < 4; i++)
        #pragma unroll
        for (int p = 0; p < 8; p++) acc[i][p] = 0.f;

    for (int ci0 = 0; ci0 < 128; ci0 += 4) {
        for (int e = tid; e < 3120; e += 256) {
            int cil = e / 780;
            int rem = e - cil*780;
            int r  = rem / 130;
            int cc = rem - r*130;
            int gr = 2*oh0 - 1 + r;
            int gc = cc - 1;
            float v = 0.f;
            if ((unsigned)gr < 128u && (unsigned)gc < 128u)
                v = x[(((size_t)b*128 + ci0 + cil)*128 + gr)*128 + gc];
            patch[cil][r][cc] = v;
        }
        #pragma unroll
        for (int e = 0; e < 16; e++) {
            int idx = tid + e*256;
            int co = idx >> 6;
            int kk = idx & 63;
            wts[kk][co] = w[(size_t)(co_base+co)*2048 + ci0*16 + kk];
        }
        __syncthreads();
        #pragma unroll
        for (int cil = 0; cil < 4; cil++)
            #pragma unroll
            for (int kh = 0; kh < 4; kh++)
                #pragma unroll
                for (int kw = 0; kw < 4; kw++) {
                    int kk = cil*16 + kh*4 + kw;
                    float w0 = wts[kk][tco*4+0], w1 = wts[kk][tco*4+1];
                    float w2 = wts[kk][tco*4+2], w3 = wts[kk][tco*4+3];
                    const float* prow = &patch[cil][2*ohl+kh][kw];
                    #pragma unroll
                    for (int pp = 0; pp < 8; pp++) {
                        float iv = prow[2*(owb+pp)];
                        acc[0][pp] += w0*iv;
                        acc[1][pp] += w1*iv;
                        acc[2][pp] += w2*iv;
                        acc[3][pp] += w3*iv;
                    }
                }
        __syncthreads();
    }
    #pragma unroll
    for (int pp = 0; pp < 8; pp++) {
        int ow = owb + pp;
        size_t token = (size_t)b*4096 + (size_t)(oh0+ohl)*64 + ow;
        float* dp = &dw[token*128 + co_base + tco*4];
        float v0 = fmaxf(acc[0][pp] + bias[co_base+tco*4+0], 0.f);
        float v1 = fmaxf(acc[1][pp] + bias[co_base+tco*4+1], 0.f);
        float v2 = fmaxf(acc[2][pp] + bias[co_base+tco*4+2], 0.f);
        float v3 = fmaxf(acc[3][pp] + bias[co_base+tco*4+3], 0.f);
        *(float4*)dp = make_float4(v0, v1, v2, v3);
    }
}

// ---------------- out = ffn*(down2x - dw) + y_img, token-major -> NCHW ----------------
__global__ void final_kernel(const float* __restrict__ x, const float* __restrict__ ffn,
                             const float* __restrict__ yt, const float* __restrict__ dwb,
                             float* __restrict__ out)
{
    int oh = blockIdx.x;   // 0..63
    int cq = blockIdx.y;   // 0..3 (32 ch)
    int b  = blockIdx.z;
    int c0 = cq*32;
    __shared__ float s_f[64*33], s_y[64*33], s_d[64*33];
    int tid = threadIdx.x;
    size_t tok0 = (size_t)b*4096 + (size_t)oh*64;
    #pragma unroll
    for (int k = 0; k < 8; k++) {
        int e = tid + k*256;
        int cl = e & 31, t = e >> 5;
        size_t ga = (tok0 + t)*128 + c0 + cl;
        s_f[t*33+cl] = ffn[ga];
        s_y[t*33+cl] = yt[ga];
        s_d[t*33+cl] = dwb[ga];
    }
    float ph = (float)oh * (127.0f/63.0f);
    int y0 = min((int)floorf(ph), 127);
    int y1 = min(y0+1, 127);
    float wy = ph - (float)y0;
    __syncthreads();
    #pragma unroll
    for (int k = 0; k < 8; k++) {
        int e = tid + k*256;
        int ow = e & 63, cl = e >> 6;
        float pw = (float)ow * (127.0f/63.0f);
        int x0 = min((int)floorf(pw), 127);
        int x1 = min(x0+1, 127);
        float wx = pw - (float)x0;
        const float* xr = x + (((size_t)b*128 + c0 + cl)*128)*128;
        float r0 = xr[(size_t)y0*128 + x0]*(1.f-wx) + xr[(size_t)y0*128 + x1]*wx;
        float r1 = xr[(size_t)y1*128 + x0]*(1.f-wx) + xr[(size_t)y1*128 + x1]*wx;
        float down = r0*(1.f-wy) + r1*wy;
        float v = s_f[ow*33+cl]*(down - s_d[ow*33+cl]) + s_y[ow*33+cl];
        out[(((size_t)b*128 + c0+cl)*64 + oh)*64 + ow] = v;
    }
}

extern "C" void kernel_launch(void* const* d_in, const int* in_sizes, int n_in,
                              void* d_out, int out_size)
{
    (void)in_sizes; (void)n_in; (void)out_size;
    const float* x      = (const float*)d_in[0];
    const float* conv1w = (const float*)d_in[1];
    const float* conv1b = (const float*)d_in[2];
    const float* l1w    = (const float*)d_in[3];
    const float* l1b    = (const float*)d_in[4];
    const float* ln1g   = (const float*)d_in[5];
    const float* ln1b   = (const float*)d_in[6];
    const float* fc1w   = (const float*)d_in[7];
    const float* fc1b   = (const float*)d_in[8];
    const float* divw   = (const float*)d_in[9];
    const float* divb   = (const float*)d_in[10];
    const float* fc2w   = (const float*)d_in[11];
    const float* fc2b   = (const float*)d_in[12];
    const float* ln3g   = (const float*)d_in[13];
    const float* ln3b   = (const float*)d_in[14];
    const float* fc3aw  = (const float*)d_in[15];
    const float* fc3ab  = (const float*)d_in[16];
    const float* fc3bw  = (const float*)d_in[17];
    const float* fc3bb  = (const float*)d_in[18];
    const float* lnng   = (const float*)d_in[19];
    const float* lnnb   = (const float*)d_in[20];
    const float* actw   = (const float*)d_in[21];
    const float* actb   = (const float*)d_in[22];
    float* out = (float*)d_out;

    float* pool = nullptr;
    cudaGetSymbolAddress((void**)&pool, g_pool);

    float* yL   = pool + 0*U;
    float* yHH  = pool + 1*U;
    float* hllh = pool + 2*U;   // 2U
    float* y    = pool + 4*U;
    float* S    = pool + 5*U;   // 4U
    float* att  = pool + 2*U;   // reuse hllh lo
    float* t1   = pool + 3*U;   // reuse hllh hi
    float* t3   = pool + 9*U;
    float* x1   = pool + 10*U;
    float* xd   = pool + 5*U;   // reuse S
    float* x2   = pool + 6*U;
    float* x3a  = pool + 7*U;
    float* x3   = pool + 8*U;
    float* gate = pool + 0*U;   // reuse yL
    float* ffn  = pool + 1*U;   // reuse yHH
    float* dw   = pool + 10*U;  // reuse x1 (dead after div gemm)
    float* cmax = pool + 11*U;
    float* csum = pool + 11*U + 65536;

    // 1. DWT
    dwt_kernel<<<dim3(64,8,16), 256>>>(x, hllh, yL, yHH);
    // 2. conv1 (1x1): y = hllh(65536,256) @ conv1w^T
    gemm_nt<<<dim3(512,1,1), 256>>>(hllh, 0, 256, conv1w, 0, 256,
                                    y, 0, 128, 256, 1.0f, conv1b, 0, nullptr);
    // 3. S = Q K^T * 8^-0.5, batched z=128 (512x512x128)
    gemm_nt<<<dim3(4,4,128), 256>>>(yL, 65536, 128, y, 65536, 128,
                                    S, 262144, 512, 128, 0.35355339059327f, nullptr, 0, nullptr);
    // 4. column softmax stats (over q)
    col_stats<<<256, 256>>>(S, cmax, csum);
    // 5. att = P @ V
    gemm_pv<<<dim3(4,1,128), 256>>>(S, yHH, cmax, csum, att);
    // 6. ln1/ln3
    ln_dual<<<8192, 256>>>(att, ln1g, ln1b, ln3g, ln3b, t1, t3);
    // 7. FFN GEMMs (65536x128x128)
    gemm_nt<<<dim3(512,1,1), 256>>>(t1, 0, 128, fc1w, 0, 128, x1, 0, 128, 128, 1.f, fc1b, 1, nullptr);
    gemm_nt<<<dim3(512,1,1), 256>>>(att, 0, 128, divw, 0, 128, xd, 0, 128, 128, 1.f, divb, 1, x1);
    gemm_nt<<<dim3(512,1,1), 256>>>(xd, 0, 128, fc2w, 0, 128, x2, 0, 128, 128, 1.f, fc2b, 1, nullptr);
    gemm_nt<<<dim3(512,1,1), 256>>>(t3, 0, 128, fc3aw, 0, 128, x3a, 0, 128, 128, 1.f, fc3ab, 1, nullptr);
    gemm_nt<<<dim3(512,1,1), 256>>>(x3a, 0, 128, fc3bw, 0, 128, x3, 0, 128, 128, 1.f, fc3bb, 0, nullptr);
    gemm_nt<<<dim3(512,1,1), 256>>>(att, 0, 128, actw, 0, 128, gate, 0, 128, 128, 1.f, actb, 2, nullptr);
    // 8. ffn = gate * ln(x2+x3)
    ln_final<<<8192, 256>>>(x2, x3, gate, lnng, lnnb, ffn);
    // 9. l1 conv
    conv_l1_kernel<<<dim3(32,2,16), 256>>>(x, l1w, l1b, dw);
    // 10. combine
    final_kernel<<<dim3(64,4,16), 256>>>(x, ffn, y, dw, out);
}

// round 5
// speedup vs baseline: 1.5327x; 1.5327x over previous
#include <cuda_runtime.h>
#include <math.h>

#define U 8388608UL
// 27U floats + stats  (~906 MB static scratch)
__device__ __align__(256) float g_pool[27*U + 131072];

// ---------------- helpers ----------------
__device__ __forceinline__ float tf32r(float v) {
    unsigned u;
    asm("cvt.rna.tf32.f32 %0, %1;" : "=r"(u) : "f"(v));
    return __uint_as_float(u);
}
__device__ __forceinline__ void mma_tf32(float* c, const unsigned* a, const unsigned* b) {
    asm volatile(
        "mma.sync.aligned.m16n8k8.row.col.f32.tf32.tf32.f32 "
        "{%0,%1,%2,%3},{%4,%5,%6,%7},{%8,%9},{%0,%1,%2,%3};"
        : "+f"(c[0]), "+f"(c[1]), "+f"(c[2]), "+f"(c[3])
        : "r"(a[0]), "r"(a[1]), "r"(a[2]), "r"(a[3]), "r"(b[0]), "r"(b[1]));
}

// ---------------- DWT ----------------
__global__ void dwt_kernel(const float* __restrict__ x, float* __restrict__ hllh,
                           float* __restrict__ yL, float* __restrict__ yHH)
{
    int i  = blockIdx.x;
    int cb = blockIdx.y;
    int b  = blockIdx.z;
    __shared__ float s[16][2][129];
    int tid = threadIdx.x;
    #pragma unroll
    for (int k = 0; k < 16; k++) {
        int e = tid + k*256;
        int cc = e >> 8, r = (e >> 7) & 1, col = e & 127;
        s[cc][r][col] = x[(((size_t)(b*128 + cb*16 + cc))*128 + 2*i + r)*128 + col];
    }
    __syncthreads();
    #pragma unroll
    for (int k = 0; k < 4; k++) {
        int e = tid + k*256;
        int cc = e & 15, j = e >> 4;
        float a  = s[cc][0][2*j], bb = s[cc][0][2*j+1];
        float c_ = s[cc][1][2*j], d  = s[cc][1][2*j+1];
        size_t token = (size_t)b*4096 + (size_t)i*64 + j;
        int c = cb*16 + cc;
        yL [token*128 + c]        = (a+bb+c_+d)*0.5f;
        yHH[token*128 + c]        = (a-bb-c_+d)*0.5f;
        hllh[token*256 + c]       = (a-bb+c_-d)*0.5f;
        hllh[token*256 + 128 + c] = (a+bb-c_-d)*0.5f;
    }
}

// ---------------- generic tf32 tensor-core NT GEMM ----------------
// BM=BN=128, BK=16, 8 warps (4m x 2n), warp tile 32x64 via m16n8k8
// C = epi(scale*A.B^T + bias) - aux ; epi: 0 none, 1 gelu, 2 sigmoid, 3 relu
__global__ __launch_bounds__(256, 2) void gemm_tf32(
    const float* __restrict__ A, size_t sAz, int lda,
    const float* __restrict__ B, size_t sBz, int ldb,
    float* __restrict__ C, size_t sCz, int ldc,
    int K, float scale, const float* __restrict__ bias,
    int epi, const float* __restrict__ aux)
{
    const float* Ab = A + (size_t)blockIdx.z * sAz;
    const float* Bb = B + (size_t)blockIdx.z * sBz;
    float* Cb = C + (size_t)blockIdx.z * sCz;
    int m0 = blockIdx.x * 128, n0 = blockIdx.y * 128;
    __shared__ float As[16][136], Bs[16][136];
    int tid = threadIdx.x;
    int wid = tid >> 5, lane = tid & 31;
    int g = lane >> 2, tig = lane & 3;
    int wm = (wid >> 1) * 32, wn = (wid & 1) * 64;
    float acc[2][8][4];
    #pragma unroll
    for (int i = 0; i < 2; i++)
        #pragma unroll
        for (int j = 0; j < 8; j++)
            #pragma unroll
            for (int q = 0; q < 4; q++) acc[i][j][q] = 0.f;

    int rowA = tid >> 2, kq = (tid & 3) * 4;
    for (int k0 = 0; k0 < K; k0 += 16) {
        #pragma unroll
        for (int e = 0; e < 2; e++) {
            int r = rowA + e*64;
            float4 va = *(const float4*)&Ab[(size_t)(m0 + r)*lda + k0 + kq];
            As[kq+0][r]=tf32r(va.x); As[kq+1][r]=tf32r(va.y);
            As[kq+2][r]=tf32r(va.z); As[kq+3][r]=tf32r(va.w);
            float4 vb = *(const float4*)&Bb[(size_t)(n0 + r)*ldb + k0 + kq];
            Bs[kq+0][r]=tf32r(vb.x); Bs[kq+1][r]=tf32r(vb.y);
            Bs[kq+2][r]=tf32r(vb.z); Bs[kq+3][r]=tf32r(vb.w);
        }
        __syncthreads();
        #pragma unroll
        for (int ks = 0; ks < 16; ks += 8) {
            unsigned af[2][4], bf[8][2];
            #pragma unroll
            for (int mi = 0; mi < 2; mi++) {
                af[mi][0] = __float_as_uint(As[ks+tig  ][wm+mi*16+g  ]);
                af[mi][1] = __float_as_uint(As[ks+tig  ][wm+mi*16+g+8]);
                af[mi][2] = __float_as_uint(As[ks+tig+4][wm+mi*16+g  ]);
                af[mi][3] = __float_as_uint(As[ks+tig+4][wm+mi*16+g+8]);
            }
            #pragma unroll
            for (int ni = 0; ni < 8; ni++) {
                bf[ni][0] = __float_as_uint(Bs[ks+tig  ][wn+ni*8+g]);
                bf[ni][1] = __float_as_uint(Bs[ks+tig+4][wn+ni*8+g]);
            }
            #pragma unroll
            for (int mi = 0; mi < 2; mi++)
                #pragma unroll
                for (int ni = 0; ni < 8; ni++)
                    mma_tf32(acc[mi][ni], af[mi], bf[ni]);
        }
        __syncthreads();
    }
    #pragma unroll
    for (int mi = 0; mi < 2; mi++)
        #pragma unroll
        for (int half = 0; half < 2; half++) {
            int m = m0 + wm + mi*16 + g + half*8;
            #pragma unroll
            for (int ni = 0; ni < 8; ni++) {
                int n = n0 + wn + ni*8 + 2*tig;
                float v0 = acc[mi][ni][half*2+0]*scale;
                float v1 = acc[mi][ni][half*2+1]*scale;
                if (bias) { v0 += bias[n]; v1 += bias[n+1]; }
                if (epi == 1) { v0 = v0*normcdff(v0); v1 = v1*normcdff(v1); }
                else if (epi == 2) { v0 = 1.f/(1.f+expf(-v0)); v1 = 1.f/(1.f+expf(-v1)); }
                else if (epi == 3) { v0 = fmaxf(v0, 0.f); v1 = fmaxf(v1, 0.f); }
                if (aux) { v0 -= aux[(size_t)m*ldc+n]; v1 -= aux[(size_t)m*ldc+n+1]; }
                *(float2*)&Cb[(size_t)m*ldc + n] = make_float2(v0, v1);
            }
        }
}

// ---------------- column softmax stats ----------------
__global__ void col_stats(const float* __restrict__ S, float* __restrict__ cmax, float* __restrict__ csum)
{
    int gidx = blockIdx.x*256 + threadIdx.x;
    int z = gidx >> 9, ki = gidx & 511;
    const float* col = S + (size_t)z*262144 + ki;
    float m[8];
    #pragma unroll
    for (int i = 0; i < 8; i++) m[i] = -1e30f;
    for (int q = 0; q < 512; q += 8)
        #pragma unroll
        for (int i = 0; i < 8; i++) m[i] = fmaxf(m[i], col[(size_t)(q+i)*512]);
    float mm = m[0];
    #pragma unroll
    for (int i = 1; i < 8; i++) mm = fmaxf(mm, m[i]);
    float s[8];
    #pragma unroll
    for (int i = 0; i < 8; i++) s[i] = 0.f;
    for (int q = 0; q < 512; q += 8)
        #pragma unroll
        for (int i = 0; i < 8; i++) s[i] += expf(col[(size_t)(q+i)*512] - mm);
    float ss = 0.f;
    #pragma unroll
    for (int i = 0; i < 8; i++) ss += s[i];
    cmax[gidx] = mm; csum[gidx] = ss;
}

// ---------------- PV GEMM (tf32): O = [exp(S-max)] @ [V/sum] ----------------
__global__ __launch_bounds__(256, 2) void gemm_pv_tf32(
    const float* __restrict__ S, const float* __restrict__ V,
    const float* __restrict__ cmax, const float* __restrict__ csum,
    float* __restrict__ O)
{
    int z = blockIdx.z;
    int m0 = blockIdx.x*128;
    const float* Sz = S + (size_t)z*262144;
    const float* Vz = V + (size_t)z*65536;
    const float* cm = cmax + z*512;
    const float* cs = csum + z*512;
    float* Oz = O + (size_t)z*65536;
    __shared__ float As[16][136], Bs[16][136];
    int tid = threadIdx.x;
    int wid = tid >> 5, lane = tid & 31;
    int g = lane >> 2, tig = lane & 3;
    int wm = (wid >> 1) * 32, wn = (wid & 1) * 64;
    float acc[2][8][4];
    #pragma unroll
    for (int i = 0; i < 2; i++)
        #pragma unroll
        for (int j = 0; j < 8; j++)
            #pragma unroll
            for (int q = 0; q < 4; q++) acc[i][j][q] = 0.f;

    int rowA = tid >> 2, kq = (tid & 3) * 4;
    int n4 = (tid & 31) * 4, kkB = tid >> 5;
    for (int k0 = 0; k0 < 512; k0 += 16) {
        #pragma unroll
        for (int e = 0; e < 2; e++) {
            int r = rowA + e*64;
            float4 va = *(const float4*)&Sz[(size_t)(m0+r)*512 + k0 + kq];
            As[kq+0][r] = tf32r(expf(va.x - cm[k0+kq+0]));
            As[kq+1][r] = tf32r(expf(va.y - cm[k0+kq+1]));
            As[kq+2][r] = tf32r(expf(va.z - cm[k0+kq+2]));
            As[kq+3][r] = tf32r(expf(va.w - cm[k0+kq+3]));
            int kk = kkB + e*8;
            float rs = 1.0f / cs[k0+kk];
            float4 vb = *(const float4*)&Vz[(size_t)(k0+kk)*128 + n4];
            Bs[kk][n4+0] = tf32r(vb.x*rs);
            Bs[kk][n4+1] = tf32r(vb.y*rs);
            Bs[kk][n4+2] = tf32r(vb.z*rs);
            Bs[kk][n4+3] = tf32r(vb.w*rs);
        }
        __syncthreads();
        #pragma unroll
        for (int ks = 0; ks < 16; ks += 8) {
            unsigned af[2][4], bf[8][2];
            #pragma unroll
            for (int mi = 0; mi < 2; mi++) {
                af[mi][0] = __float_as_uint(As[ks+tig  ][wm+mi*16+g  ]);
                af[mi][1] = __float_as_uint(As[ks+tig  ][wm+mi*16+g+8]);
                af[mi][2] = __float_as_uint(As[ks+tig+4][wm+mi*16+g  ]);
                af[mi][3] = __float_as_uint(As[ks+tig+4][wm+mi*16+g+8]);
            }
            #pragma unroll
            for (int ni = 0; ni < 8; ni++) {
                bf[ni][0] = __float_as_uint(Bs[ks+tig  ][wn+ni*8+g]);
                bf[ni][1] = __float_as_uint(Bs[ks+tig+4][wn+ni*8+g]);
            }
            #pragma unroll
            for (int mi = 0; mi < 2; mi++)
                #pragma unroll
                for (int ni = 0; ni < 8; ni++)
                    mma_tf32(acc[mi][ni], af[mi], bf[ni]);
        }
        __syncthreads();
    }
    #pragma unroll
    for (int mi = 0; mi < 2; mi++)
        #pragma unroll
        for (int half = 0; half < 2; half++) {
            int m = m0 + wm + mi*16 + g + half*8;
            #pragma unroll
            for (int ni = 0; ni < 8; ni++) {
                int n = wn + ni*8 + 2*tig;
                *(float2*)&Oz[(size_t)m*128 + n] =
                    make_float2(acc[mi][ni][half*2+0], acc[mi][ni][half*2+1]);
            }
        }
}

// ---------------- im2col for l1 conv (4x4, s2, p1) ----------------
__global__ void im2col_l1(const float* __restrict__ x, float* __restrict__ col)
{
    int oh = blockIdx.x;      // 0..63
    int cb = blockIdx.y;      // 0..15 (8 ci each)
    int b  = blockIdx.z;
    __shared__ float s[8][4][132];
    int tid = threadIdx.x;
    for (int e = tid; e < 4160; e += 256) {
        int cil = e / 520;
        int rem = e - cil*520;
        int r = rem / 130, cc = rem - r*130;
        int gr = 2*oh - 1 + r, gc = cc - 1;
        float v = 0.f;
        if ((unsigned)gr < 128u && (unsigned)gc < 128u)
            v = x[(((size_t)b*128 + cb*8 + cil)*128 + gr)*128 + gc];
        s[cil][r][cc] = v;
    }
    __syncthreads();
    int t = tid >> 2, vq = (tid & 3) * 32;
    size_t base = ((size_t)b*4096 + (size_t)oh*64 + t)*2048 + cb*128 + vq;
    #pragma unroll
    for (int i = 0; i < 32; i += 4) {
        int v0 = vq + i;
        int cil = v0 >> 4, kh = (v0 >> 2) & 3;
        const float* p = &s[cil][kh][2*t];
        *(float4*)&col[base + i] = make_float4(p[0], p[1], p[2], p[3]);
    }
}

// ---------------- dual layernorm ----------------
__global__ void ln_dual(const float* __restrict__ X,
                        const float* __restrict__ g1v, const float* __restrict__ b1v,
                        const float* __restrict__ g3v, const float* __restrict__ b3v,
                        float* __restrict__ t1, float* __restrict__ t3)
{
    int wrp = threadIdx.x >> 5, lane = threadIdx.x & 31;
    size_t token = (size_t)blockIdx.x*8 + wrp;
    const float4 v = *(const float4*)&X[token*128 + lane*4];
    float s  = v.x+v.y+v.z+v.w;
    float ss = v.x*v.x+v.y*v.y+v.z*v.z+v.w*v.w;
    #pragma unroll
    for (int o = 16; o; o >>= 1) {
        s  += __shfl_xor_sync(0xffffffffu, s,  o);
        ss += __shfl_xor_sync(0xffffffffu, ss, o);
    }
    float mean = s * (1.f/128.f);
    float rstd = rsqrtf(ss*(1.f/128.f) - mean*mean + 1e-5f);
    float4 G = *(const float4*)&g1v[lane*4];
    float4 Bv = *(const float4*)&b1v[lane*4];
    float4 o1;
    o1.x = (v.x-mean)*rstd*G.x + Bv.x;
    o1.y = (v.y-mean)*rstd*G.y + Bv.y;
    o1.z = (v.z-mean)*rstd*G.z + Bv.z;
    o1.w = (v.w-mean)*rstd*G.w + Bv.w;
    *(float4*)&t1[token*128 + lane*4] = o1;
    G  = *(const float4*)&g3v[lane*4];
    Bv = *(const float4*)&b3v[lane*4];
    o1.x = (v.x-mean)*rstd*G.x + Bv.x;
    o1.y = (v.y-mean)*rstd*G.y + Bv.y;
    o1.z = (v.z-mean)*rstd*G.z + Bv.z;
    o1.w = (v.w-mean)*rstd*G.w + Bv.w;
    *(float4*)&t3[token*128 + lane*4] = o1;
}

// ---------------- out = gate * ln(x2+x3) ----------------
__global__ void ln_final(const float* __restrict__ X2, const float* __restrict__ X3,
                         const float* __restrict__ G, const float* __restrict__ gv,
                         const float* __restrict__ bv, float* __restrict__ out)
{
    int wrp = threadIdx.x >> 5, lane = threadIdx.x & 31;
    size_t token = (size_t)blockIdx.x*8 + wrp;
    float4 a = *(const float4*)&X2[token*128 + lane*4];
    float4 c = *(const float4*)&X3[token*128 + lane*4];
    float4 v = make_float4(a.x+c.x, a.y+c.y, a.z+c.z, a.w+c.w);
    float s  = v.x+v.y+v.z+v.w;
    float ss = v.x*v.x+v.y*v.y+v.z*v.z+v.w*v.w;
    #pragma unroll
    for (int o = 16; o; o >>= 1) {
        s  += __shfl_xor_sync(0xffffffffu, s,  o);
        ss += __shfl_xor_sync(0xffffffffu, ss, o);
    }
    float mean = s * (1.f/128.f);
    float rstd = rsqrtf(ss*(1.f/128.f) - mean*mean + 1e-5f);
    float4 g = *(const float4*)&gv[lane*4];
    float4 b = *(const float4*)&bv[lane*4];
    float4 gt = *(const float4*)&G[token*128 + lane*4];
    float4 o;
    o.x = gt.x * ((v.x-mean)*rstd*g.x + b.x);
    o.y = gt.y * ((v.y-mean)*rstd*g.y + b.y);
    o.z = gt.z * ((v.z-mean)*rstd*g.z + b.z);
    o.w = gt.w * ((v.w-mean)*rstd*g.w + b.w);
    *(float4*)&out[token*128 + lane*4] = o;
}

// ---------------- final combine ----------------
__global__ void final_kernel(const float* __restrict__ x, const float* __restrict__ ffn,
                             const float* __restrict__ yt, const float* __restrict__ dwb,
                             float* __restrict__ out)
{
    int oh = blockIdx.x;
    int cq = blockIdx.y;
    int b  = blockIdx.z;
    int c0 = cq*32;
    __shared__ float s_f[64*33], s_y[64*33], s_d[64*33];
    int tid = threadIdx.x;
    size_t tok0 = (size_t)b*4096 + (size_t)oh*64;
    #pragma unroll
    for (int k = 0; k < 8; k++) {
        int e = tid + k*256;
        int cl = e & 31, t = e >> 5;
        size_t ga = (tok0 + t)*128 + c0 + cl;
        s_f[t*33+cl] = ffn[ga];
        s_y[t*33+cl] = yt[ga];
        s_d[t*33+cl] = dwb[ga];
    }
    float ph = (float)oh * (127.0f/63.0f);
    int y0 = min((int)floorf(ph), 127);
    int y1 = min(y0+1, 127);
    float wy = ph - (float)y0;
    __syncthreads();
    #pragma unroll
    for (int k = 0; k < 8; k++) {
        int e = tid + k*256;
        int ow = e & 63, cl = e >> 6;
        float pw = (float)ow * (127.0f/63.0f);
        int x0 = min((int)floorf(pw), 127);
        int x1 = min(x0+1, 127);
        float wx = pw - (float)x0;
        const float* xr = x + (((size_t)b*128 + c0 + cl)*128)*128;
        float r0 = xr[(size_t)y0*128 + x0]*(1.f-wx) + xr[(size_t)y0*128 + x1]*wx;
        float r1 = xr[(size_t)y1*128 + x0]*(1.f-wx) + xr[(size_t)y1*128 + x1]*wx;
        float down = r0*(1.f-wy) + r1*wy;
        float v = s_f[ow*33+cl]*(down - s_d[ow*33+cl]) + s_y[ow*33+cl];
        out[(((size_t)b*128 + c0+cl)*64 + oh)*64 + ow] = v;
    }
}

extern "C" void kernel_launch(void* const* d_in, const int* in_sizes, int n_in,
                              void* d_out, int out_size)
{
    (void)in_sizes; (void)n_in; (void)out_size;
    const float* x      = (const float*)d_in[0];
    const float* conv1w = (const float*)d_in[1];
    const float* conv1b = (const float*)d_in[2];
    const float* l1w    = (const float*)d_in[3];
    const float* l1b    = (const float*)d_in[4];
    const float* ln1g   = (const float*)d_in[5];
    const float* ln1b   = (const float*)d_in[6];
    const float* fc1w   = (const float*)d_in[7];
    const float* fc1b   = (const float*)d_in[8];
    const float* divw   = (const float*)d_in[9];
    const float* divb   = (const float*)d_in[10];
    const float* fc2w   = (const float*)d_in[11];
    const float* fc2b   = (const float*)d_in[12];
    const float* ln3g   = (const float*)d_in[13];
    const float* ln3b   = (const float*)d_in[14];
    const float* fc3aw  = (const float*)d_in[15];
    const float* fc3ab  = (const float*)d_in[16];
    const float* fc3bw  = (const float*)d_in[17];
    const float* fc3bb  = (const float*)d_in[18];
    const float* lnng   = (const float*)d_in[19];
    const float* lnnb   = (const float*)d_in[20];
    const float* actw   = (const float*)d_in[21];
    const float* actb   = (const float*)d_in[22];
    float* out = (float*)d_out;

    float* pool = nullptr;
    cudaGetSymbolAddress((void**)&pool, g_pool);

    float* yL   = pool + 0*U;
    float* yHH  = pool + 1*U;
    float* hllh = pool + 2*U;   // 2U
    float* y    = pool + 4*U;
    float* S    = pool + 5*U;   // 4U
    float* att  = pool + 2*U;
    float* t1   = pool + 3*U;
    float* t3   = pool + 9*U;
    float* x1   = pool + 10*U;
    float* xd   = pool + 5*U;
    float* x2   = pool + 6*U;
    float* x3a  = pool + 7*U;
    float* x3   = pool + 8*U;
    float* gate = pool + 0*U;
    float* ffn  = pool + 1*U;
    float* dw   = pool + 10*U;
    float* colb = pool + 11*U;  // 16U im2col
    float* cmax = pool + 27*U;
    float* csum = pool + 27*U + 65536;

    // 1. DWT
    dwt_kernel<<<dim3(64,8,16), 256>>>(x, hllh, yL, yHH);
    // 2. conv1 (1x1 as GEMM)
    gemm_tf32<<<dim3(512,1,1), 256>>>(hllh, 0, 256, conv1w, 0, 256,
                                      y, 0, 128, 256, 1.0f, conv1b, 0, nullptr);
    // 3. S = Q K^T * 8^-0.5
    gemm_tf32<<<dim3(4,4,128), 256>>>(yL, 65536, 128, y, 65536, 128,
                                      S, 262144, 512, 128, 0.35355339059327f, nullptr, 0, nullptr);
    // 4. column softmax stats
    col_stats<<<256, 256>>>(S, cmax, csum);
    // 5. att = P @ V
    gemm_pv_tf32<<<dim3(4,1,128), 256>>>(S, yHH, cmax, csum, att);
    // 6. ln1/ln3
    ln_dual<<<8192, 256>>>(att, ln1g, ln1b, ln3g, ln3b, t1, t3);
    // 7. FFN GEMMs
    gemm_tf32<<<dim3(512,1,1), 256>>>(t1, 0, 128, fc1w, 0, 128, x1, 0, 128, 128, 1.f, fc1b, 1, nullptr);
    gemm_tf32<<<dim3(512,1,1), 256>>>(att, 0, 128, divw, 0, 128, xd, 0, 128, 128, 1.f, divb, 1, x1);
    gemm_tf32<<<dim3(512,1,1), 256>>>(xd, 0, 128, fc2w, 0, 128, x2, 0, 128, 128, 1.f, fc2b, 1, nullptr);
    gemm_tf32<<<dim3(512,1,1), 256>>>(t3, 0, 128, fc3aw, 0, 128, x3a, 0, 128, 128, 1.f, fc3ab, 1, nullptr);
    gemm_tf32<<<dim3(512,1,1), 256>>>(x3a, 0, 128, fc3bw, 0, 128, x3, 0, 128, 128, 1.f, fc3bb, 0, nullptr);
    gemm_tf32<<<dim3(512,1,1), 256>>>(att, 0, 128, actw, 0, 128, gate, 0, 128, 128, 1.f, actb, 2, nullptr);
    // 8. ffn = gate * ln(x2+x3)
    ln_final<<<8192, 256>>>(x2, x3, gate, lnng, lnnb, ffn);
    // 9. l1 conv = im2col + tf32 GEMM (relu)
    im2col_l1<<<dim3(64,16,16), 256>>>(x, colb);
    gemm_tf32<<<dim3(512,1,1), 256>>>(colb, 0, 2048, l1w, 0, 2048,
                                      dw, 0, 128, 2048, 1.f, l1b, 3, nullptr);
    // 10. combine
    final_kernel<<<dim3(64,4,16), 256>>>(x, ffn, y, dw, out);
}

// round 6
// speedup vs baseline: 2.0226x; 1.3196x over previous
#include <cuda_runtime.h>
#include <math.h>

#define U 8388608UL
__device__ __align__(256) float g_pool[11*U + 131072];

// ---------------- helpers ----------------
__device__ __forceinline__ float tf32r(float v) {
    unsigned u;
    asm("cvt.rna.tf32.f32 %0, %1;" : "=r"(u) : "f"(v));
    return __uint_as_float(u);
}
__device__ __forceinline__ void mma_tf32(float* c, const unsigned* a, const unsigned* b) {
    asm volatile(
        "mma.sync.aligned.m16n8k8.row.col.f32.tf32.tf32.f32 "
        "{%0,%1,%2,%3},{%4,%5,%6,%7},{%8,%9},{%0,%1,%2,%3};"
        : "+f"(c[0]), "+f"(c[1]), "+f"(c[2]), "+f"(c[3])
        : "r"(a[0]), "r"(a[1]), "r"(a[2]), "r"(a[3]), "r"(b[0]), "r"(b[1]));
}

// ---------------- DWT ----------------
__global__ void dwt_kernel(const float* __restrict__ x, float* __restrict__ hllh,
                           float* __restrict__ yL, float* __restrict__ yHH)
{
    int i  = blockIdx.x;
    int cb = blockIdx.y;
    int b  = blockIdx.z;
    __shared__ float s[16][2][129];
    int tid = threadIdx.x;
    #pragma unroll
    for (int k = 0; k < 16; k++) {
        int e = tid + k*256;
        int cc = e >> 8, r = (e >> 7) & 1, col = e & 127;
        s[cc][r][col] = x[(((size_t)(b*128 + cb*16 + cc))*128 + 2*i + r)*128 + col];
    }
    __syncthreads();
    #pragma unroll
    for (int k = 0; k < 4; k++) {
        int e = tid + k*256;
        int cc = e & 15, j = e >> 4;
        float a  = s[cc][0][2*j], bb = s[cc][0][2*j+1];
        float c_ = s[cc][1][2*j], d  = s[cc][1][2*j+1];
        size_t token = (size_t)b*4096 + (size_t)i*64 + j;
        int c = cb*16 + cc;
        yL [token*128 + c]        = (a+bb+c_+d)*0.5f;
        yHH[token*128 + c]        = (a-bb-c_+d)*0.5f;
        hllh[token*256 + c]       = (a-bb+c_-d)*0.5f;
        hllh[token*256 + 128 + c] = (a+bb-c_-d)*0.5f;
    }
}

// ---------------- tf32 NT GEMM with register prefetch ----------------
__global__ __launch_bounds__(256, 2) void gemm_tf32(
    const float* __restrict__ A, size_t sAz, int lda,
    const float* __restrict__ B, size_t sBz, int ldb,
    float* __restrict__ C, size_t sCz, int ldc,
    int K, float scale, const float* __restrict__ bias,
    int epi, const float* __restrict__ aux)
{
    const float* Ab = A + (size_t)blockIdx.z * sAz;
    const float* Bb = B + (size_t)blockIdx.z * sBz;
    float* Cb = C + (size_t)blockIdx.z * sCz;
    int m0 = blockIdx.x * 128, n0 = blockIdx.y * 128;
    __shared__ float As[16][136], Bs[16][136];
    int tid = threadIdx.x;
    int wid = tid >> 5, lane = tid & 31;
    int g = lane >> 2, tig = lane & 3;
    int wm = (wid >> 1) * 32, wn = (wid & 1) * 64;
    float acc[2][8][4];
    #pragma unroll
    for (int i = 0; i < 2; i++)
        #pragma unroll
        for (int j = 0; j < 8; j++)
            #pragma unroll
            for (int q = 0; q < 4; q++) acc[i][j][q] = 0.f;

    int rowA = tid >> 2, kq = (tid & 3) * 4;
    float4 pa[2], pb[2];
    #pragma unroll
    for (int e = 0; e < 2; e++) {
        int r = rowA + e*64;
        pa[e] = *(const float4*)&Ab[(size_t)(m0 + r)*lda + kq];
        pb[e] = *(const float4*)&Bb[(size_t)(n0 + r)*ldb + kq];
    }
    for (int k0 = 0; k0 < K; k0 += 16) {
        #pragma unroll
        for (int e = 0; e < 2; e++) {
            int r = rowA + e*64;
            As[kq+0][r]=tf32r(pa[e].x); As[kq+1][r]=tf32r(pa[e].y);
            As[kq+2][r]=tf32r(pa[e].z); As[kq+3][r]=tf32r(pa[e].w);
            Bs[kq+0][r]=tf32r(pb[e].x); Bs[kq+1][r]=tf32r(pb[e].y);
            Bs[kq+2][r]=tf32r(pb[e].z); Bs[kq+3][r]=tf32r(pb[e].w);
        }
        __syncthreads();
        if (k0 + 16 < K) {
            #pragma unroll
            for (int e = 0; e < 2; e++) {
                int r = rowA + e*64;
                pa[e] = *(const float4*)&Ab[(size_t)(m0 + r)*lda + k0 + 16 + kq];
                pb[e] = *(const float4*)&Bb[(size_t)(n0 + r)*ldb + k0 + 16 + kq];
            }
        }
        #pragma unroll
        for (int ks = 0; ks < 16; ks += 8) {
            unsigned af[2][4], bf[8][2];
            #pragma unroll
            for (int mi = 0; mi < 2; mi++) {
                af[mi][0] = __float_as_uint(As[ks+tig  ][wm+mi*16+g  ]);
                af[mi][1] = __float_as_uint(As[ks+tig  ][wm+mi*16+g+8]);
                af[mi][2] = __float_as_uint(As[ks+tig+4][wm+mi*16+g  ]);
                af[mi][3] = __float_as_uint(As[ks+tig+4][wm+mi*16+g+8]);
            }
            #pragma unroll
            for (int ni = 0; ni < 8; ni++) {
                bf[ni][0] = __float_as_uint(Bs[ks+tig  ][wn+ni*8+g]);
                bf[ni][1] = __float_as_uint(Bs[ks+tig+4][wn+ni*8+g]);
            }
            #pragma unroll
            for (int mi = 0; mi < 2; mi++)
                #pragma unroll
                for (int ni = 0; ni < 8; ni++)
                    mma_tf32(acc[mi][ni], af[mi], bf[ni]);
        }
        __syncthreads();
    }
    #pragma unroll
    for (int mi = 0; mi < 2; mi++)
        #pragma unroll
        for (int half = 0; half < 2; half++) {
            int m = m0 + wm + mi*16 + g + half*8;
            #pragma unroll
            for (int ni = 0; ni < 8; ni++) {
                int n = n0 + wn + ni*8 + 2*tig;
                float v0 = acc[mi][ni][half*2+0]*scale;
                float v1 = acc[mi][ni][half*2+1]*scale;
                if (bias) { v0 += bias[n]; v1 += bias[n+1]; }
                if (epi == 1) { v0 = v0*normcdff(v0); v1 = v1*normcdff(v1); }
                else if (epi == 2) { v0 = 1.f/(1.f+expf(-v0)); v1 = 1.f/(1.f+expf(-v1)); }
                if (aux) { v0 -= aux[(size_t)m*ldc+n]; v1 -= aux[(size_t)m*ldc+n+1]; }
                *(float2*)&Cb[(size_t)m*ldc + n] = make_float2(v0, v1);
            }
        }
}

// ---------------- fused implicit-GEMM l1 conv (4x4, s2, p1, relu) ----------------
__global__ __launch_bounds__(256, 2) void conv_l1_tf32(
    const float* __restrict__ x, const float* __restrict__ w,
    const float* __restrict__ bias, float* __restrict__ dw)
{
    int blk = blockIdx.x;     // 0..31 : 2 output rows
    int b   = blockIdx.z;
    int oh0 = blk*2;
    __shared__ float patch[8][6][132];
    __shared__ float As[16][136], Bs[16][136];
    int tid = threadIdx.x;
    int wid = tid >> 5, lane = tid & 31;
    int g = lane >> 2, tig = lane & 3;
    int wm = (wid >> 1) * 32, wn = (wid & 1) * 64;
    float acc[2][8][4];
    #pragma unroll
    for (int i = 0; i < 2; i++)
        #pragma unroll
        for (int j = 0; j < 8; j++)
            #pragma unroll
            for (int q = 0; q < 4; q++) acc[i][j][q] = 0.f;

    int t = tid & 127, kkq = (tid >> 7) * 8;
    int ohl = t >> 6, ow = t & 63;
    int coB = tid >> 1, kbB = (tid & 1) * 8;

    for (int ci0 = 0; ci0 < 128; ci0 += 8) {
        // stage 8ci x 6rows x 130cols patch (tf32-rounded)
        for (int e = tid; e < 8*6*130; e += 256) {
            int cil = e / 780;
            int rem = e - cil*780;
            int r = rem / 130, cc = rem - r*130;
            int gr = 2*oh0 - 1 + r, gc = cc - 1;
            float v = 0.f;
            if ((unsigned)gr < 128u && (unsigned)gc < 128u)
                v = x[(((size_t)b*128 + ci0 + cil)*128 + gr)*128 + gc];
            patch[cil][r][cc] = tf32r(v);
        }
        __syncthreads();
        #pragma unroll 1
        for (int cil = 0; cil < 8; cil++) {
            int kbase = (ci0 + cil) * 16;
            #pragma unroll
            for (int i = 0; i < 8; i++) {
                int kk = kkq + i;
                int kh = kk >> 2, kw = kk & 3;
                As[kk][t] = patch[cil][2*ohl + kh][2*ow + kw];
            }
            {
                float4 w0 = *(const float4*)&w[(size_t)coB*2048 + kbase + kbB];
                float4 w1 = *(const float4*)&w[(size_t)coB*2048 + kbase + kbB + 4];
                Bs[kbB+0][coB]=tf32r(w0.x); Bs[kbB+1][coB]=tf32r(w0.y);
                Bs[kbB+2][coB]=tf32r(w0.z); Bs[kbB+3][coB]=tf32r(w0.w);
                Bs[kbB+4][coB]=tf32r(w1.x); Bs[kbB+5][coB]=tf32r(w1.y);
                Bs[kbB+6][coB]=tf32r(w1.z); Bs[kbB+7][coB]=tf32r(w1.w);
            }
            __syncthreads();
            #pragma unroll
            for (int ks = 0; ks < 16; ks += 8) {
                unsigned af[2][4], bf[8][2];
                #pragma unroll
                for (int mi = 0; mi < 2; mi++) {
                    af[mi][0] = __float_as_uint(As[ks+tig  ][wm+mi*16+g  ]);
                    af[mi][1] = __float_as_uint(As[ks+tig  ][wm+mi*16+g+8]);
                    af[mi][2] = __float_as_uint(As[ks+tig+4][wm+mi*16+g  ]);
                    af[mi][3] = __float_as_uint(As[ks+tig+4][wm+mi*16+g+8]);
                }
                #pragma unroll
                for (int ni = 0; ni < 8; ni++) {
                    bf[ni][0] = __float_as_uint(Bs[ks+tig  ][wn+ni*8+g]);
                    bf[ni][1] = __float_as_uint(Bs[ks+tig+4][wn+ni*8+g]);
                }
                #pragma unroll
                for (int mi = 0; mi < 2; mi++)
                    #pragma unroll
                    for (int ni = 0; ni < 8; ni++)
                        mma_tf32(acc[mi][ni], af[mi], bf[ni]);
            }
            __syncthreads();
        }
    }
    #pragma unroll
    for (int mi = 0; mi < 2; mi++)
        #pragma unroll
        for (int half = 0; half < 2; half++) {
            int midx = wm + mi*16 + g + half*8;
            size_t token = (size_t)b*4096 + (size_t)blk*128 + midx;
            #pragma unroll
            for (int ni = 0; ni < 8; ni++) {
                int n = wn + ni*8 + 2*tig;
                float v0 = fmaxf(acc[mi][ni][half*2+0] + bias[n],   0.f);
                float v1 = fmaxf(acc[mi][ni][half*2+1] + bias[n+1], 0.f);
                *(float2*)&dw[token*128 + n] = make_float2(v0, v1);
            }
        }
}

// ---------------- single-pass online column softmax stats ----------------
__global__ void col_stats(const float* __restrict__ S, float* __restrict__ cmax, float* __restrict__ csum)
{
    int gidx = blockIdx.x*256 + threadIdx.x;
    int z = gidx >> 9, ki = gidx & 511;
    const float* col = S + (size_t)z*262144 + ki;
    float m = -1e30f, s = 0.f;
    for (int q = 0; q < 512; q += 16) {
        float v[16];
        #pragma unroll
        for (int i = 0; i < 16; i++) v[i] = col[(size_t)(q+i)*512];
        float lm = v[0];
        #pragma unroll
        for (int i = 1; i < 16; i++) lm = fmaxf(lm, v[i]);
        float nm = fmaxf(m, lm);
        float acc = 0.f;
        #pragma unroll
        for (int i = 0; i < 16; i++) acc += expf(v[i] - nm);
        s = s * expf(m - nm) + acc;
        m = nm;
    }
    cmax[gidx] = m; csum[gidx] = s;
}

// ---------------- PV GEMM (tf32) with prefetch ----------------
__global__ __launch_bounds__(256, 2) void gemm_pv_tf32(
    const float* __restrict__ S, const float* __restrict__ V,
    const float* __restrict__ cmax, const float* __restrict__ csum,
    float* __restrict__ O)
{
    int z = blockIdx.z;
    int m0 = blockIdx.x*128;
    const float* Sz = S + (size_t)z*262144;
    const float* Vz = V + (size_t)z*65536;
    const float* cm = cmax + z*512;
    const float* cs = csum + z*512;
    float* Oz = O + (size_t)z*65536;
    __shared__ float As[16][136], Bs[16][136];
    int tid = threadIdx.x;
    int wid = tid >> 5, lane = tid & 31;
    int g = lane >> 2, tig = lane & 3;
    int wm = (wid >> 1) * 32, wn = (wid & 1) * 64;
    float acc[2][8][4];
    #pragma unroll
    for (int i = 0; i < 2; i++)
        #pragma unroll
        for (int j = 0; j < 8; j++)
            #pragma unroll
            for (int q = 0; q < 4; q++) acc[i][j][q] = 0.f;

    int rowA = tid >> 2, kq = (tid & 3) * 4;
    int n4 = (tid & 31) * 4, kkB = tid >> 5;
    float4 pa[2], pb[2], pcm;
    float pcs[2];
    #pragma unroll
    for (int e = 0; e < 2; e++) {
        pa[e] = *(const float4*)&Sz[(size_t)(m0 + rowA + e*64)*512 + kq];
        pb[e] = *(const float4*)&Vz[(size_t)(kkB + e*8)*128 + n4];
        pcs[e] = cs[kkB + e*8];
    }
    pcm = *(const float4*)&cm[kq];
    for (int k0 = 0; k0 < 512; k0 += 16) {
        #pragma unroll
        for (int e = 0; e < 2; e++) {
            int r = rowA + e*64;
            As[kq+0][r] = tf32r(expf(pa[e].x - pcm.x));
            As[kq+1][r] = tf32r(expf(pa[e].y - pcm.y));
            As[kq+2][r] = tf32r(expf(pa[e].z - pcm.z));
            As[kq+3][r] = tf32r(expf(pa[e].w - pcm.w));
            int kk = kkB + e*8;
            float rs = 1.0f / pcs[e];
            Bs[kk][n4+0] = tf32r(pb[e].x*rs);
            Bs[kk][n4+1] = tf32r(pb[e].y*rs);
            Bs[kk][n4+2] = tf32r(pb[e].z*rs);
            Bs[kk][n4+3] = tf32r(pb[e].w*rs);
        }
        __syncthreads();
        if (k0 + 16 < 512) {
            #pragma unroll
            for (int e = 0; e < 2; e++) {
                pa[e] = *(const float4*)&Sz[(size_t)(m0 + rowA + e*64)*512 + k0 + 16 + kq];
                pb[e] = *(const float4*)&Vz[(size_t)(k0 + 16 + kkB + e*8)*128 + n4];
                pcs[e] = cs[k0 + 16 + kkB + e*8];
            }
            pcm = *(const float4*)&cm[k0 + 16 + kq];
        }
        #pragma unroll
        for (int ks = 0; ks < 16; ks += 8) {
            unsigned af[2][4], bf[8][2];
            #pragma unroll
            for (int mi = 0; mi < 2; mi++) {
                af[mi][0] = __float_as_uint(As[ks+tig  ][wm+mi*16+g  ]);
                af[mi][1] = __float_as_uint(As[ks+tig  ][wm+mi*16+g+8]);
                af[mi][2] = __float_as_uint(As[ks+tig+4][wm+mi*16+g  ]);
                af[mi][3] = __float_as_uint(As[ks+tig+4][wm+mi*16+g+8]);
            }
            #pragma unroll
            for (int ni = 0; ni < 8; ni++) {
                bf[ni][0] = __float_as_uint(Bs[ks+tig  ][wn+ni*8+g]);
                bf[ni][1] = __float_as_uint(Bs[ks+tig+4][wn+ni*8+g]);
            }
            #pragma unroll
            for (int mi = 0; mi < 2; mi++)
                #pragma unroll
                for (int ni = 0; ni < 8; ni++)
                    mma_tf32(acc[mi][ni], af[mi], bf[ni]);
        }
        __syncthreads();
    }
    #pragma unroll
    for (int mi = 0; mi < 2; mi++)
        #pragma unroll
        for (int half = 0; half < 2; half++) {
            int m = m0 + wm + mi*16 + g + half*8;
            #pragma unroll
            for (int ni = 0; ni < 8; ni++) {
                int n = wn + ni*8 + 2*tig;
                *(float2*)&Oz[(size_t)m*128 + n] =
                    make_float2(acc[mi][ni][half*2+0], acc[mi][ni][half*2+1]);
            }
        }
}

// ---------------- dual layernorm ----------------
__global__ void ln_dual(const float* __restrict__ X,
                        const float* __restrict__ g1v, const float* __restrict__ b1v,
                        const float* __restrict__ g3v, const float* __restrict__ b3v,
                        float* __restrict__ t1, float* __restrict__ t3)
{
    int wrp = threadIdx.x >> 5, lane = threadIdx.x & 31;
    size_t token = (size_t)blockIdx.x*8 + wrp;
    const float4 v = *(const float4*)&X[token*128 + lane*4];
    float s  = v.x+v.y+v.z+v.w;
    float ss = v.x*v.x+v.y*v.y+v.z*v.z+v.w*v.w;
    #pragma unroll
    for (int o = 16; o; o >>= 1) {
        s  += __shfl_xor_sync(0xffffffffu, s,  o);
        ss += __shfl_xor_sync(0xffffffffu, ss, o);
    }
    float mean = s * (1.f/128.f);
    float rstd = rsqrtf(ss*(1.f/128.f) - mean*mean + 1e-5f);
    float4 G = *(const float4*)&g1v[lane*4];
    float4 Bv = *(const float4*)&b1v[lane*4];
    float4 o1;
    o1.x = (v.x-mean)*rstd*G.x + Bv.x;
    o1.y = (v.y-mean)*rstd*G.y + Bv.y;
    o1.z = (v.z-mean)*rstd*G.z + Bv.z;
    o1.w = (v.w-mean)*rstd*G.w + Bv.w;
    *(float4*)&t1[token*128 + lane*4] = o1;
    G  = *(const float4*)&g3v[lane*4];
    Bv = *(const float4*)&b3v[lane*4];
    o1.x = (v.x-mean)*rstd*G.x + Bv.x;
    o1.y = (v.y-mean)*rstd*G.y + Bv.y;
    o1.z = (v.z-mean)*rstd*G.z + Bv.z;
    o1.w = (v.w-mean)*rstd*G.w + Bv.w;
    *(float4*)&t3[token*128 + lane*4] = o1;
}

// ---------------- out = gate * ln(x2+x3) ----------------
__global__ void ln_final(const float* __restrict__ X2, const float* __restrict__ X3,
                         const float* __restrict__ G, const float* __restrict__ gv,
                         const float* __restrict__ bv, float* __restrict__ out)
{
    int wrp = threadIdx.x >> 5, lane = threadIdx.x & 31;
    size_t token = (size_t)blockIdx.x*8 + wrp;
    float4 a = *(const float4*)&X2[token*128 + lane*4];
    float4 c = *(const float4*)&X3[token*128 + lane*4];
    float4 v = make_float4(a.x+c.x, a.y+c.y, a.z+c.z, a.w+c.w);
    float s  = v.x+v.y+v.z+v.w;
    float ss = v.x*v.x+v.y*v.y+v.z*v.z+v.w*v.w;
    #pragma unroll
    for (int o = 16; o; o >>= 1) {
        s  += __shfl_xor_sync(0xffffffffu, s,  o);
        ss += __shfl_xor_sync(0xffffffffu, ss, o);
    }
    float mean = s * (1.f/128.f);
    float rstd = rsqrtf(ss*(1.f/128.f) - mean*mean + 1e-5f);
    float4 g = *(const float4*)&gv[lane*4];
    float4 b = *(const float4*)&bv[lane*4];
    float4 gt = *(const float4*)&G[token*128 + lane*4];
    float4 o;
    o.x = gt.x * ((v.x-mean)*rstd*g.x + b.x);
    o.y = gt.y * ((v.y-mean)*rstd*g.y + b.y);
    o.z = gt.z * ((v.z-mean)*rstd*g.z + b.z);
    o.w = gt.w * ((v.w-mean)*rstd*g.w + b.w);
    *(float4*)&out[token*128 + lane*4] = o;
}

// ---------------- final combine ----------------
__global__ void final_kernel(const float* __restrict__ x, const float* __restrict__ ffn,
                             const float* __restrict__ yt, const float* __restrict__ dwb,
                             float* __restrict__ out)
{
    int oh = blockIdx.x;
    int cq = blockIdx.y;
    int b  = blockIdx.z;
    int c0 = cq*32;
    __shared__ float s_f[64*33], s_y[64*33], s_d[64*33];
    int tid = threadIdx.x;
    size_t tok0 = (size_t)b*4096 + (size_t)oh*64;
    #pragma unroll
    for (int k = 0; k < 8; k++) {
        int e = tid + k*256;
        int cl = e & 31, t = e >> 5;
        size_t ga = (tok0 + t)*128 + c0 + cl;
        s_f[t*33+cl] = ffn[ga];
        s_y[t*33+cl] = yt[ga];
        s_d[t*33+cl] = dwb[ga];
    }
    float ph = (float)oh * (127.0f/63.0f);
    int y0 = min((int)floorf(ph), 127);
    int y1 = min(y0+1, 127);
    float wy = ph - (float)y0;
    __syncthreads();
    #pragma unroll
    for (int k = 0; k < 8; k++) {
        int e = tid + k*256;
        int ow = e & 63, cl = e >> 6;
        float pw = (float)ow * (127.0f/63.0f);
        int x0 = min((int)floorf(pw), 127);
        int x1 = min(x0+1, 127);
        float wx = pw - (float)x0;
        const float* xr = x + (((size_t)b*128 + c0 + cl)*128)*128;
        float r0 = xr[(size_t)y0*128 + x0]*(1.f-wx) + xr[(size_t)y0*128 + x1]*wx;
        float r1 = xr[(size_t)y1*128 + x0]*(1.f-wx) + xr[(size_t)y1*128 + x1]*wx;
        float down = r0*(1.f-wy) + r1*wy;
        float v = s_f[ow*33+cl]*(down - s_d[ow*33+cl]) + s_y[ow*33+cl];
        out[(((size_t)b*128 + c0+cl)*64 + oh)*64 + ow] = v;
    }
}

extern "C" void kernel_launch(void* const* d_in, const int* in_sizes, int n_in,
                              void* d_out, int out_size)
{
    (void)in_sizes; (void)n_in; (void)out_size;
    const float* x      = (const float*)d_in[0];
    const float* conv1w = (const float*)d_in[1];
    const float* conv1b = (const float*)d_in[2];
    const float* l1w    = (const float*)d_in[3];
    const float* l1b    = (const float*)d_in[4];
    const float* ln1g   = (const float*)d_in[5];
    const float* ln1b   = (const float*)d_in[6];
    const float* fc1w   = (const float*)d_in[7];
    const float* fc1b   = (const float*)d_in[8];
    const float* divw   = (const float*)d_in[9];
    const float* divb   = (const float*)d_in[10];
    const float* fc2w   = (const float*)d_in[11];
    const float* fc2b   = (const float*)d_in[12];
    const float* ln3g   = (const float*)d_in[13];
    const float* ln3b   = (const float*)d_in[14];
    const float* fc3aw  = (const float*)d_in[15];
    const float* fc3ab  = (const float*)d_in[16];
    const float* fc3bw  = (const float*)d_in[17];
    const float* fc3bb  = (const float*)d_in[18];
    const float* lnng   = (const float*)d_in[19];
    const float* lnnb   = (const float*)d_in[20];
    const float* actw   = (const float*)d_in[21];
    const float* actb   = (const float*)d_in[22];
    float* out = (float*)d_out;

    float* pool = nullptr;
    cudaGetSymbolAddress((void**)&pool, g_pool);

    float* yL   = pool + 0*U;
    float* yHH  = pool + 1*U;
    float* hllh = pool + 2*U;   // 2U
    float* y    = pool + 4*U;
    float* S    = pool + 5*U;   // 4U (5U..9U)
    float* att  = pool + 2*U;
    float* t1   = pool + 3*U;
    float* t3   = pool + 9*U;
    float* x1   = pool + 10*U;
    float* xd   = pool + 5*U;
    float* x2   = pool + 6*U;
    float* x3a  = pool + 7*U;
    float* x3   = pool + 8*U;
    float* gate = pool + 0*U;
    float* ffn  = pool + 1*U;
    float* dw   = pool + 10*U;
    float* cmax = pool + 11*U - 131072;   // tail (after x1 dead region? keep separate)
    float* csum = cmax + 65536;
    // NOTE: cmax/csum must not overlap live buffers: place them past 11U instead
    cmax = pool + 11*U;  // uses the +131072 tail of the pool
    csum = pool + 11*U + 65536;

    // 1. DWT
    dwt_kernel<<<dim3(64,8,16), 256>>>(x, hllh, yL, yHH);
    // 2. conv1 (1x1 as GEMM)
    gemm_tf32<<<dim3(512,1,1), 256>>>(hllh, 0, 256, conv1w, 0, 256,
                                      y, 0, 128, 256, 1.0f, conv1b, 0, nullptr);
    // 3. S = Q K^T * 8^-0.5
    gemm_tf32<<<dim3(4,4,128), 256>>>(yL, 65536, 128, y, 65536, 128,
                                      S, 262144, 512, 128, 0.35355339059327f, nullptr, 0, nullptr);
    // 4. column softmax stats (single pass, online)
    col_stats<<<256, 256>>>(S, cmax, csum);
    // 5. att = P @ V
    gemm_pv_tf32<<<dim3(4,1,128), 256>>>(S, yHH, cmax, csum, att);
    // 6. ln1/ln3
    ln_dual<<<8192, 256>>>(att, ln1g, ln1b, ln3g, ln3b, t1, t3);
    // 7. FFN GEMMs
    gemm_tf32<<<dim3(512,1,1), 256>>>(t1, 0, 128, fc1w, 0, 128, x1, 0, 128, 128, 1.f, fc1b, 1, nullptr);
    gemm_tf32<<<dim3(512,1,1), 256>>>(att, 0, 128, divw, 0, 128, xd, 0, 128, 128, 1.f, divb, 1, x1);
    gemm_tf32<<<dim3(512,1,1), 256>>>(xd, 0, 128, fc2w, 0, 128, x2, 0, 128, 128, 1.f, fc2b, 1, nullptr);
    gemm_tf32<<<dim3(512,1,1), 256>>>(t3, 0, 128, fc3aw, 0, 128, x3a, 0, 128, 128, 1.f, fc3ab, 1, nullptr);
    gemm_tf32<<<dim3(512,1,1), 256>>>(x3a, 0, 128, fc3bw, 0, 128, x3, 0, 128, 128, 1.f, fc3bb, 0, nullptr);
    gemm_tf32<<<dim3(512,1,1), 256>>>(att, 0, 128, actw, 0, 128, gate, 0, 128, 128, 1.f, actb, 2, nullptr);
    // 8. ffn = gate * ln(x2+x3)
    ln_final<<<8192, 256>>>(x2, x3, gate, lnng, lnnb, ffn);
    // 9. fused implicit-GEMM l1 conv
    conv_l1_tf32<<<dim3(32,1,16), 256>>>(x, l1w, l1b, dw);
    // 10. combine
    final_kernel<<<dim3(64,4,16), 256>>>(x, ffn, y, dw, out);
}